// round 5
// baseline (speedup 1.0000x reference)
#include <cuda_runtime.h>
#include <cstdint>
#include <math.h>

#define TOKENS 32768
#define NEXP   64
#define KDIM   2048
#define KC     32              // floats per K-chunk (2 k16 steps)
#define NCH    (KDIM / KC)     // 64 chunks
#define TILE_M 128
#define TPB    256
#define NKB16  (KDIM / 16)     // 128 k16 blocks
#define STAGES 4

// W pre-split, fragment-ready bf16: [kb16(128)][nf(8)][lane(32)] = {bh0,bh1,bm0,bm1}
__device__ uint4 g_wperm[NKB16 * 8 * 32];   // 512 KB

static __device__ __forceinline__ uint32_t bfpack(float hi, float lo) {
    uint32_t d;
    asm("cvt.rn.bf16x2.f32 %0, %1, %2;" : "=r"(d) : "f"(hi), "f"(lo));
    return d;
}
static __device__ __forceinline__ float bflo(uint32_t p) { return __uint_as_float(p << 16); }
static __device__ __forceinline__ float bfhi(uint32_t p) { return __uint_as_float(p & 0xFFFF0000u); }

static __device__ __forceinline__ void split_pair(float a, float b, uint32_t& h, uint32_t& m) {
    h = bfpack(b, a);                       // lo = a, hi = b
    m = bfpack(b - bfhi(h), a - bflo(h));
}

static __device__ __forceinline__ void mma16(float* d, const uint32_t* a,
                                             uint32_t b0, uint32_t b1) {
    asm volatile(
        "mma.sync.aligned.m16n8k16.row.col.f32.bf16.bf16.f32 "
        "{%0,%1,%2,%3}, {%4,%5,%6,%7}, {%8,%9}, {%0,%1,%2,%3};"
        : "+f"(d[0]), "+f"(d[1]), "+f"(d[2]), "+f"(d[3])
        : "r"(a[0]), "r"(a[1]), "r"(a[2]), "r"(a[3]), "r"(b0), "r"(b1));
}
static __device__ __forceinline__ void merge2(float& v1, int& i1, float& v2, int& i2, int off) {
    float ov1 = __shfl_xor_sync(0xffffffffu, v1, off);
    int   oi1 = __shfl_xor_sync(0xffffffffu, i1, off);
    float ov2 = __shfl_xor_sync(0xffffffffu, v2, off);
    int   oi2 = __shfl_xor_sync(0xffffffffu, i2, off);
    bool mine = (v1 > ov1) || (v1 == ov1 && i1 < oi1);
    float l1v = mine ? ov1 : v1;  int l1i = mine ? oi1 : i1;
    float s2v = mine ? v2  : ov2; int s2i = mine ? i2  : oi2;
    v1 = mine ? v1 : ov1;  i1 = mine ? i1 : oi1;
    bool sec = (s2v > l1v) || (s2v == l1v && s2i < l1i);
    v2 = sec ? s2v : l1v;  i2 = sec ? s2i : l1i;
}

// barrier ids: full_s = 1+s (producers arrive, consumers sync)
//              empty_s = 5+s (consumers arrive, producers sync)
static __device__ __forceinline__ void bar_sync(int id) {
    asm volatile("bar.sync %0, %1;" :: "r"(id), "r"(TPB) : "memory");
}
static __device__ __forceinline__ void bar_arrive(int id) {
    asm volatile("bar.arrive %0, %1;" :: "r"(id), "r"(TPB) : "memory");
}

// ---- prep: split W into bf16 fragment-ready layout (once per launch) ----
extern "C" __global__ void __launch_bounds__(256)
prep_w(const float* __restrict__ W)
{
    int idx  = blockIdx.x * 256 + threadIdx.x;  // 0..32767
    int lane = idx & 31;
    int nf   = (idx >> 5) & 7;
    int kb   = idx >> 8;                        // k16 block 0..127
    int g = lane >> 2, t = lane & 3;
    const float* wr = W + (size_t)(nf * 8 + g) * KDIM + kb * 16;
    uint4 r;
    split_pair(wr[2 * t],     wr[2 * t + 1], r.x, r.z);   // b0 (k = 2t, 2t+1)
    split_pair(wr[2 * t + 8], wr[2 * t + 9], r.y, r.w);   // b1 (k = 2t+8, 2t+9)
    g_wperm[idx] = r;
}

// SMEM per stage (uint4 units): aH[512] | aM[512] | B[512]  -> 1536 uint4 = 24KB
#define STAGE_U4  1536
#define SMEM_BYTES (STAGES * STAGE_U4 * 16)   // 98304

extern "C" __global__ void __launch_bounds__(TPB, 2)
router_bf16(const float* __restrict__ X, float* __restrict__ out)
{
    extern __shared__ uint4 sm4[];
    const int tid  = threadIdx.x;
    const int wid  = tid >> 5;
    const int lane = tid & 31;
    const int g    = lane >> 2;
    const int t    = lane & 3;
    const int blockM = blockIdx.x * TILE_M;

    if (wid >= 4) {
        // ---------------- producers: warps 4..7, double-buffered regs ----------------
        const int p = tid - 128;   // 0..127
        float4 xa[2][4], xb[2][4];
        uint4  bb[2][4];

        #define PLOAD(c, rb)                                                        \
            {                                                                       \
                _Pragma("unroll")                                                   \
                for (int j = 0; j < 4; j++) {                                       \
                    int s_idx = p + 128 * j;          /* 0..511 */                  \
                    int row = s_idx >> 2, q2 = s_idx & 3;                           \
                    const float* src = X + (size_t)(blockM + row) * KDIM            \
                                         + (size_t)(c) * KC + q2 * 8;               \
                    xa[rb][j] = reinterpret_cast<const float4*>(src)[0];            \
                    xb[rb][j] = reinterpret_cast<const float4*>(src)[1];            \
                    bb[rb][j] = g_wperm[(c) * 512 + s_idx];                         \
                }                                                                   \
            }
        #define PSTORE(c, rb)                                                       \
            {                                                                       \
                uint4* aH = sm4 + ((c) & (STAGES - 1)) * STAGE_U4;                  \
                uint4* aM = aH + 512;                                               \
                uint4* sB = aH + 1024;                                              \
                _Pragma("unroll")                                                   \
                for (int j = 0; j < 4; j++) {                                       \
                    int s_idx = p + 128 * j;                                        \
                    int row = s_idx >> 2, q2 = s_idx & 3;                           \
                    uint4 H, M;                                                     \
                    split_pair(xa[rb][j].x, xa[rb][j].y, H.x, M.x);                 \
                    split_pair(xa[rb][j].z, xa[rb][j].w, H.y, M.y);                 \
                    split_pair(xb[rb][j].x, xb[rb][j].y, H.z, M.z);                 \
                    split_pair(xb[rb][j].z, xb[rb][j].w, H.w, M.w);                 \
                    int a_idx = q2 * 128 + (row ^ (2 * q2));                        \
                    aH[a_idx]  = H;                                                 \
                    aM[a_idx]  = M;                                                 \
                    sB[s_idx]  = bb[rb][j];                                         \
                }                                                                   \
            }

        PLOAD(0, 0);
        PLOAD(1, 1);

        for (int c = 0; c < NCH; c++) {
            if (c >= STAGES) bar_sync(5 + (c & (STAGES - 1)));   // wait stage empty
            PSTORE(c, c & 1);
            bar_arrive(1 + (c & (STAGES - 1)));                  // publish stage full
            if (c + 2 < NCH) PLOAD(c + 2, c & 1);
        }
        return;
    }

    // ---------------- consumers: warps 0..3, tile m32 x n64 ----------------
    float acc[2][8][4];
    #pragma unroll
    for (int mf = 0; mf < 2; mf++)
        #pragma unroll
        for (int nf = 0; nf < 8; nf++)
            #pragma unroll
            for (int u = 0; u < 4; u++) acc[mf][nf][u] = 0.0f;

    const int wbase = wid * 32;

    for (int c = 0; c < NCH; c++) {
        const int s = c & (STAGES - 1);
        bar_sync(1 + s);                                          // wait stage full
        const uint32_t* aH = reinterpret_cast<const uint32_t*>(sm4 + s * STAGE_U4);
        const uint32_t* aM = aH + 2048;
        const uint4*    sB = sm4 + s * STAGE_U4 + 1024;

        #pragma unroll
        for (int kb = 0; kb < 2; kb++) {
            uint32_t ah[2][4], am[2][4];
            #pragma unroll
            for (int mf = 0; mf < 2; mf++) {
                const int R0 = wbase + mf * 16 + g;
                const int i0 = ((2 * kb) * 128 + (R0 ^ (4 * kb))) * 4 + t;
                const int i2 = ((2 * kb + 1) * 128 + (R0 ^ (4 * kb + 2))) * 4 + t;
                ah[mf][0] = aH[i0];       ah[mf][1] = aH[i0 + 32];
                ah[mf][2] = aH[i2];       ah[mf][3] = aH[i2 + 32];
                am[mf][0] = aM[i0];       am[mf][1] = aM[i0 + 32];
                am[mf][2] = aM[i2];       am[mf][3] = aM[i2 + 32];
            }
            #pragma unroll
            for (int nf = 0; nf < 8; nf++) {
                uint4 b = sB[(kb * 8 + nf) * 32 + lane];
                #pragma unroll
                for (int mf = 0; mf < 2; mf++) {
                    mma16(acc[mf][nf], ah[mf], b.x, b.y);   // Ah*Bh
                    mma16(acc[mf][nf], ah[mf], b.z, b.w);   // Ah*Bm
                    mma16(acc[mf][nf], am[mf], b.x, b.y);   // Am*Bh
                }
            }
        }
        bar_arrive(5 + s);                                        // release stage
    }

    // ---------------- epilogue: logits + stable top-2 + softmax ----------------
    float* outIdx = out;
    float* outWgt = out + TOKENS * 2;
    float* outLog = out + TOKENS * 4;

    #pragma unroll
    for (int mf = 0; mf < 2; mf++) {
        #pragma unroll
        for (int h = 0; h < 2; h++) {
            const int row = wbase + mf * 16 + h * 8 + g;
            const int tok = blockM + row;

            float v1 = -INFINITY, v2 = -INFINITY;
            int   i1 = 0, i2 = 0;
            #pragma unroll
            for (int nf = 0; nf < 8; nf++) {
                #pragma unroll
                for (int u = 0; u < 2; u++) {
                    float v  = acc[mf][nf][2 * h + u];
                    int   id = nf * 8 + 2 * t + u;
                    if (v > v1)      { v2 = v1; i2 = i1; v1 = v; i1 = id; }
                    else if (v > v2) { v2 = v;  i2 = id; }
                }
            }
            merge2(v1, i1, v2, i2, 1);
            merge2(v1, i1, v2, i2, 2);

            float* lr = outLog + (size_t)tok * NEXP;
            #pragma unroll
            for (int nf = 0; nf < 8; nf++) {
                float2 o = make_float2(acc[mf][nf][2 * h], acc[mf][nf][2 * h + 1]);
                *reinterpret_cast<float2*>(lr + nf * 8 + 2 * t) = o;
            }

            if (t == 0) {
                float e2  = expf(v2 - v1);          // v1 >= v2 -> stable
                float inv = 1.0f / (1.0f + e2);
                outIdx[tok * 2]     = (float)i1;
                outIdx[tok * 2 + 1] = (float)i2;
                outWgt[tok * 2]     = inv;
                outWgt[tok * 2 + 1] = e2 * inv;
            }
        }
    }
}

extern "C" void kernel_launch(void* const* d_in, const int* in_sizes, int n_in,
                              void* d_out, int out_size)
{
    const float* X = (const float*)d_in[0];   // [32768, 2048] fp32
    const float* W = (const float*)d_in[1];   // [64, 2048] fp32
    float* out = (float*)d_out;

    prep_w<<<128, 256>>>(W);

    cudaFuncSetAttribute(router_bf16,
                         cudaFuncAttributeMaxDynamicSharedMemorySize, SMEM_BYTES);
    router_bf16<<<TOKENS / TILE_M, TPB, SMEM_BYTES>>>(X, out);
}